// round 10
// baseline (speedup 1.0000x reference)
#include <cuda_runtime.h>
#include <cstdint>

// Problem constants
#define BB   2
#define SS   2048
#define TT   2048
#define CHN  1024
#define NH   16
#define HD   64
#define MM   (BB * SS)   // 4096 rows

// Scratch (device globals: allocation-free rule)
__device__ float g_Q[(size_t)MM * CHN];
__device__ float g_K[(size_t)MM * CHN];
__device__ float g_V[(size_t)MM * CHN];
__device__ float g_A[(size_t)MM * CHN];

// ---------------- helpers ----------------
__device__ __forceinline__ uint32_t f2tf(float x) {
    uint32_t u;
    asm("cvt.rna.tf32.f32 %0, %1;\n" : "=r"(u) : "f"(x));
    return u;
}
__device__ __forceinline__ float f2tf_f(float x) {
    return __uint_as_float(f2tf(x));
}
__device__ __forceinline__ uint32_t fu(float x) { return __float_as_uint(x); }

__device__ __forceinline__ float4 tf4(float4 v) {
    return make_float4(f2tf_f(v.x), f2tf_f(v.y), f2tf_f(v.z), f2tf_f(v.w));
}

__device__ __forceinline__ uint32_t smem_u32(const void* p) {
    return (uint32_t)__cvta_generic_to_shared(p);
}

// D(16x8) += A(16x8, tf32, row) * B(8x8, tf32, col)
__device__ __forceinline__ void mma8(float c[4], const uint32_t a[4], const uint32_t b[2]) {
    asm volatile(
        "mma.sync.aligned.m16n8k8.row.col.f32.tf32.tf32.f32 "
        "{%0,%1,%2,%3}, {%4,%5,%6,%7}, {%8,%9}, {%0,%1,%2,%3};\n"
        : "+f"(c[0]), "+f"(c[1]), "+f"(c[2]), "+f"(c[3])
        : "r"(a[0]), "r"(a[1]), "r"(a[2]), "r"(a[3]), "r"(b[0]), "r"(b[1]));
}

// ldmatrix x4: 4 8x8-b16 matrices (= 8x4-tf32 blocks). Lane L of matrix j gets
// the 32-bit word at (row L/4, col L%4) -> exact tf32 mma fragment layout.
__device__ __forceinline__ void ldsm_x4(uint32_t r[4], uint32_t saddr) {
    asm volatile("ldmatrix.sync.aligned.m8n8.x4.shared.b16 {%0,%1,%2,%3}, [%4];"
        : "=r"(r[0]), "=r"(r[1]), "=r"(r[2]), "=r"(r[3]) : "r"(saddr));
}

// ---------------- GEMM: C[4096,1024] = X @ W + bias ----------------
// UNCHANGED from R9 (proven 64.5us each). BM=128, BN=128, BK=32, 256 threads.
#define GXF   (128 * 36)
#define GWF   (128 * 36)
#define GSTG  (GXF + GWF)
#define GSTGB (GSTG * 4)

__global__ void __launch_bounds__(256, 2) gemm_bias_kernel(
    const float* __restrict__ X, const float* __restrict__ W,
    const float* __restrict__ bias, float* __restrict__ C,
    const float* __restrict__ maskScale)
{
    extern __shared__ float gsm[];   // 2 stages
    const uint32_t gsb = smem_u32(gsm);

    const int tid  = threadIdx.x;
    const int lane = tid & 31;
    const int warp = tid >> 5;
    const int g    = lane >> 2;
    const int tg   = lane & 3;
    const int wm   = warp >> 1;   // 0..3
    const int wn   = warp & 1;    // 0..1
    const int m0   = blockIdx.y * 128;
    const int n0   = blockIdx.x * 128;

    const uint32_t a_thr = (uint32_t)(((wm * 32 + (lane & 15)) * 36 + (lane >> 4) * 4) * 4);
    const uint32_t b_thr = (uint32_t)(((wn * 64 + ((lane >> 4) * 8) + (lane & 7)) * 36
                                      + (((lane >> 3) & 1) * 4)) * 4);

    float4 px[4], pw[4];

    auto ldg_tile = [&](int kt) {
#pragma unroll
        for (int i = 0; i < 4; i++) {
            int idx = i * 256 + tid;
            int xr = idx >> 3, xc = (idx & 7) * 4;
            px[i] = *(const float4*)&X[(size_t)(m0 + xr) * 1024 + kt + xc];
        }
        const int bn = tid & 127;
        const int bh = tid >> 7;
#pragma unroll
        for (int j = 0; j < 4; j++) {
            int kq = bh * 4 + j;
            pw[j] = make_float4(
                W[(size_t)(kt + kq * 4 + 0) * 1024 + n0 + bn],
                W[(size_t)(kt + kq * 4 + 1) * 1024 + n0 + bn],
                W[(size_t)(kt + kq * 4 + 2) * 1024 + n0 + bn],
                W[(size_t)(kt + kq * 4 + 3) * 1024 + n0 + bn]);
        }
    };
    auto sts_tile = [&](int st) {
        float* Xs = gsm + st * GSTG;
        float* Ws = Xs + GXF;
#pragma unroll
        for (int i = 0; i < 4; i++) {
            int idx = i * 256 + tid;
            int xr = idx >> 3, xc = (idx & 7) * 4;
            *(float4*)&Xs[xr * 36 + xc] = tf4(px[i]);
        }
        const int bn = tid & 127;
        const int bh = tid >> 7;
#pragma unroll
        for (int j = 0; j < 4; j++) {
            int kq = bh * 4 + j;
            *(float4*)&Ws[bn * 36 + kq * 4] = tf4(pw[j]);
        }
    };

    float c[2][8][4];
#pragma unroll
    for (int mt = 0; mt < 2; mt++)
#pragma unroll
        for (int nt = 0; nt < 8; nt++)
#pragma unroll
            for (int e = 0; e < 4; e++) c[mt][nt][e] = 0.f;

    ldg_tile(0);
    sts_tile(0);
    __syncthreads();

    for (int kt = 0; kt < 32; kt++) {
        if (kt + 1 < 32) ldg_tile((kt + 1) * 32);

        const uint32_t xa = gsb + (kt & 1) * GSTGB + a_thr;
        const uint32_t wa = gsb + (kt & 1) * GSTGB + GXF * 4 + b_thr;

#pragma unroll
        for (int kk = 0; kk < 4; kk++) {
            uint32_t af[2][4], bf[4][4];
            ldsm_x4(af[0], xa + kk * 32);
            ldsm_x4(af[1], xa + 16 * 36 * 4 + kk * 32);
#pragma unroll
            for (int p = 0; p < 4; p++)
                ldsm_x4(bf[p], wa + p * (16 * 36 * 4) + kk * 32);
#pragma unroll
            for (int p = 0; p < 4; p++) {
                mma8(c[0][2 * p],     af[0], &bf[p][0]);
                mma8(c[0][2 * p + 1], af[0], &bf[p][2]);
                mma8(c[1][2 * p],     af[1], &bf[p][0]);
                mma8(c[1][2 * p + 1], af[1], &bf[p][2]);
            }
        }

        if (kt + 1 < 32) sts_tile((kt + 1) & 1);
        __syncthreads();
    }

#pragma unroll
    for (int mt = 0; mt < 2; mt++) {
        int r0 = m0 + wm * 32 + mt * 16 + g;
        int r1 = r0 + 8;
        float sc0 = 1.f, sc1 = 1.f;
        if (maskScale) {
            sc0 = maskScale[(size_t)r0 * TT];
            sc1 = maskScale[(size_t)r1 * TT];
        }
#pragma unroll
        for (int nt = 0; nt < 8; nt++) {
            int col = n0 + wn * 64 + nt * 8 + 2 * tg;
            float b0 = bias[col], b1 = bias[col + 1];
            float2 v0 = make_float2((c[mt][nt][0] + b0) * sc0, (c[mt][nt][1] + b1) * sc0);
            float2 v1 = make_float2((c[mt][nt][2] + b0) * sc1, (c[mt][nt][3] + b1) * sc1);
            *(float2*)&C[(size_t)r0 * 1024 + col] = v0;
            *(float2*)&C[(size_t)r1 * 1024 + col] = v1;
        }
    }
}

// ---------------- Flash attention v5: 8 warps, 1 m-tile/warp ----------------
// Grid: (S/128, H, B), 256 threads = 8 warps; warp w owns q-rows [16w, 16w+16).
// Lower per-warp registers -> 2 CTAs/SM = 16 warps/SM (2x R9 occupancy) to
// hide the serial softmax chain. LDSM fragments throughout.
// Ks: [t][d] stride 68. Vs: [d][t] stride 68 (transposed fill).
// P round-trips through this warp's 16 Qs rows (Q frags persist in regs).
#define LDS_  68
#define FCH   64
#define NCH   (TT / FCH)

__global__ void __launch_bounds__(256, 2) flash_attn_kernel(
    const float* __restrict__ mask, const int* __restrict__ causal_p)
{
    extern __shared__ float sm[];
    float* Qs = sm;                     // 128 x 68
    float* Ks = sm + 128 * LDS_;        // 64 x 68  [t][d]
    float* Vs = sm + 192 * LDS_;        // 64 x 68  [d][t]

    const int tid  = threadIdx.x;
    const int lane = tid & 31;
    const int warp = tid >> 5;          // 0..7
    const int g    = lane >> 2;
    const int tg   = lane & 3;
    const int s0   = blockIdx.x * 128;
    const int h    = blockIdx.y;
    const int b    = blockIdx.z;
    const int causal = causal_p[0];

    const uint32_t Qs_u = smem_u32(Qs);
    const uint32_t Ks_u = smem_u32(Ks);
    const uint32_t Vs_u = smem_u32(Vs);

    // LDSM per-thread bases (bytes)
    const uint32_t bK = Ks_u + (uint32_t)(((((lane >> 4) * 8) + (lane & 7)) * LDS_
                                           + (((lane >> 3) & 1) * 4)) * 4);
    const uint32_t bV = Vs_u + (uint32_t)(((((lane >> 4) * 8) + (lane & 7)) * LDS_
                                           + (((lane >> 3) & 1) * 4)) * 4);
    const uint32_t aP = Qs_u + (uint32_t)(((warp * 16 + (lane & 15)) * LDS_
                                           + ((lane >> 4) * 4)) * 4);

    // Load Q tile [128 x 64] -> smem (tf32-rounded); 2048 float4 / 256 thr
    const size_t qoff = ((size_t)b * SS + s0) * CHN + h * HD;
#pragma unroll
    for (int i = 0; i < 8; i++) {
        int idx = i * 256 + tid;
        int r = idx >> 4, cc = (idx & 15) * 4;
        float4 v = *(const float4*)&g_Q[qoff + (size_t)r * CHN + cc];
        *(float4*)&Qs[r * LDS_ + cc] = tf4(v);
    }
    __syncthreads();

    // Persistent Q fragments: 8 k-steps x 4 regs (32 regs)
    uint32_t qa[8][4];
#pragma unroll
    for (int j = 0; j < 8; j++) ldsm_x4(qa[j], aP + j * 32);

    float o[8][4];
#pragma unroll
    for (int nt = 0; nt < 8; nt++)
#pragma unroll
        for (int e = 0; e < 4; e++) o[nt][e] = 0.f;
    float m0r = -1e30f, m1r = -1e30f, l0r = 0.f, l1r = 0.f;

    const float* mb = mask + (size_t)b * SS * TT;
    const int vd  = tid & 63;     // V transpose: this thread's d row
    const int vth = tid >> 6;     // 0..3: t-quad group

    for (int ic = 0; ic < NCH; ic++) {
        const int t0 = ic * FCH;
        __syncthreads();

        const size_t kvoff = ((size_t)b * TT + t0) * CHN + h * HD;
        // K fill [t][d]: 1024 float4 / 256 thr
#pragma unroll
        for (int i = 0; i < 4; i++) {
            int idx = i * 256 + tid;
            int r = idx >> 4, cc = (idx & 15) * 4;
            float4 kv = *(const float4*)&g_K[kvoff + (size_t)r * CHN + cc];
            *(float4*)&Ks[r * LDS_ + cc] = tf4(kv);
        }
        // V fill transposed [d][t]: thread owns d=vd, 4 t-quads
#pragma unroll
        for (int q4 = 0; q4 < 4; q4++) {
            int q = vth * 4 + q4;   // t-quad 0..15
            float4 vv = make_float4(
                g_V[kvoff + (size_t)(q * 4 + 0) * CHN + vd],
                g_V[kvoff + (size_t)(q * 4 + 1) * CHN + vd],
                g_V[kvoff + (size_t)(q * 4 + 2) * CHN + vd],
                g_V[kvoff + (size_t)(q * 4 + 3) * CHN + vd]);
            *(float4*)&Vs[vd * LDS_ + q * 4] = tf4(vv);
        }
        __syncthreads();

        // S = Q K^T : warp's 16 rows x 64 cols
        float s[8][4];
#pragma unroll
        for (int nt = 0; nt < 8; nt++)
#pragma unroll
            for (int e = 0; e < 4; e++) s[nt][e] = 0.f;
#pragma unroll
        for (int ks = 0; ks < 8; ks++) {
            uint32_t kf[4][4];
#pragma unroll
            for (int p = 0; p < 4; p++)
                ldsm_x4(kf[p], bK + p * (16 * LDS_ * 4) + ks * 32);
#pragma unroll
            for (int p = 0; p < 4; p++) {
                mma8(s[2 * p],     qa[ks], &kf[p][0]);
                mma8(s[2 * p + 1], qa[ks], &kf[p][2]);
            }
        }

        // Scale + mask (reference semantics)
        if (!causal) {
#pragma unroll
            for (int nt = 0; nt < 8; nt++) {
#pragma unroll
                for (int e = 0; e < 2; e++) {
                    bool mz = (mb[t0 + nt * 8 + 2 * tg + e] == 0.f);
                    s[nt][e]     = mz ? -1e30f : s[nt][e] * 0.125f;
                    s[nt][2 + e] = mz ? -1e30f : s[nt][2 + e] * 0.125f;
                }
            }
        } else {
            int rg0 = s0 + warp * 16 + g;
            int rg1 = rg0 + 8;
#pragma unroll
            for (int nt = 0; nt < 8; nt++) {
#pragma unroll
                for (int e = 0; e < 2; e++) {
                    int t = t0 + nt * 8 + 2 * tg + e;
                    float v0 = s[nt][e] * 0.125f;
                    float v1 = s[nt][2 + e] * 0.125f;
                    if (mb[(size_t)rg0 * TT + t] == 0.f && t <= rg0) v0 = -1e30f;
                    if (mb[(size_t)rg1 * TT + t] == 0.f && t <= rg1) v1 = -1e30f;
                    s[nt][e] = v0;
                    s[nt][2 + e] = v1;
                }
            }
        }

        // Online softmax; write P into own 16 Qs rows
        {
            float rm0 = -1e30f, rm1 = -1e30f;
#pragma unroll
            for (int nt = 0; nt < 8; nt++) {
                rm0 = fmaxf(rm0, fmaxf(s[nt][0], s[nt][1]));
                rm1 = fmaxf(rm1, fmaxf(s[nt][2], s[nt][3]));
            }
            rm0 = fmaxf(rm0, __shfl_xor_sync(0xffffffffu, rm0, 1));
            rm0 = fmaxf(rm0, __shfl_xor_sync(0xffffffffu, rm0, 2));
            rm1 = fmaxf(rm1, __shfl_xor_sync(0xffffffffu, rm1, 1));
            rm1 = fmaxf(rm1, __shfl_xor_sync(0xffffffffu, rm1, 2));

            float mn0 = fmaxf(m0r, rm0);
            float mn1 = fmaxf(m1r, rm1);
            float a0 = __expf(m0r - mn0);
            float a1 = __expf(m1r - mn1);
            m0r = mn0; m1r = mn1;

            int rb = warp * 16;
            float ls0 = 0.f, ls1 = 0.f;
#pragma unroll
            for (int nt = 0; nt < 8; nt++) {
                float p00 = __expf(s[nt][0] - mn0);
                float p01 = __expf(s[nt][1] - mn0);
                float p10 = __expf(s[nt][2] - mn1);
                float p11 = __expf(s[nt][3] - mn1);
                ls0 += p00 + p01;
                ls1 += p10 + p11;
                int cb = nt * 8 + 2 * tg;
                *(float2*)&Qs[(rb + g) * LDS_ + cb] =
                    make_float2(f2tf_f(p00), f2tf_f(p01));
                *(float2*)&Qs[(rb + g + 8) * LDS_ + cb] =
                    make_float2(f2tf_f(p10), f2tf_f(p11));
                o[nt][0] *= a0; o[nt][1] *= a0;
                o[nt][2] *= a1; o[nt][3] *= a1;
            }
            ls0 += __shfl_xor_sync(0xffffffffu, ls0, 1);
            ls0 += __shfl_xor_sync(0xffffffffu, ls0, 2);
            ls1 += __shfl_xor_sync(0xffffffffu, ls1, 1);
            ls1 += __shfl_xor_sync(0xffffffffu, ls1, 2);
            l0r = l0r * a0 + ls0;
            l1r = l1r * a1 + ls1;
        }
        __syncwarp();   // P visible within warp before LDSM of own rows

        // O += P V
#pragma unroll
        for (int ks = 0; ks < 8; ks++) {
            uint32_t pf[4], vf[4][4];
            ldsm_x4(pf, aP + ks * 32);
#pragma unroll
            for (int p = 0; p < 4; p++)
                ldsm_x4(vf[p], bV + p * (16 * LDS_ * 4) + ks * 32);
#pragma unroll
            for (int p = 0; p < 4; p++) {
                mma8(o[2 * p],     pf, &vf[p][0]);
                mma8(o[2 * p + 1], pf, &vf[p][2]);
            }
        }
    }

    // Normalize and write out
    {
        float i0 = 1.f / l0r;
        float i1 = 1.f / l1r;
        const size_t ob = ((size_t)b * SS + s0 + warp * 16) * CHN + h * HD;
#pragma unroll
        for (int nt = 0; nt < 8; nt++) {
            int col = nt * 8 + 2 * tg;
            float2 v0 = make_float2(o[nt][0] * i0, o[nt][1] * i0);
            float2 v1 = make_float2(o[nt][2] * i1, o[nt][3] * i1);
            *(float2*)&g_A[ob + (size_t)g * CHN + col] = v0;
            *(float2*)&g_A[ob + (size_t)(g + 8) * CHN + col] = v1;
        }
    }
}

// ---------------- launch ----------------
extern "C" void kernel_launch(void* const* d_in, const int* in_sizes, int n_in,
                              void* d_out, int out_size)
{
    const float* query = (const float*)d_in[0];
    const float* key   = (const float*)d_in[1];
    const float* value = (const float*)d_in[2];
    const float* mask  = (const float*)d_in[3];
    const float* Wq    = (const float*)d_in[4];
    const float* bq    = (const float*)d_in[5];
    const float* Wk    = (const float*)d_in[6];
    const float* bk    = (const float*)d_in[7];
    const float* Wv    = (const float*)d_in[8];
    const float* bv    = (const float*)d_in[9];
    const float* Wo    = (const float*)d_in[10];
    const float* bo    = (const float*)d_in[11];
    const int*   causal = (const int*)d_in[12];
    float* out = (float*)d_out;

    float *Qp, *Kp, *Vp, *Ap;
    cudaGetSymbolAddress((void**)&Qp, g_Q);
    cudaGetSymbolAddress((void**)&Kp, g_K);
    cudaGetSymbolAddress((void**)&Vp, g_V);
    cudaGetSymbolAddress((void**)&Ap, g_A);

    const int gsmem = 2 * GSTGB;   // 73,728 B
    cudaFuncSetAttribute(gemm_bias_kernel,
                         cudaFuncAttributeMaxDynamicSharedMemorySize, gsmem);

    dim3 ggrid(8, 32);   // N/128, M/128
    gemm_bias_kernel<<<ggrid, 256, gsmem>>>(query, Wq, bq, Qp, nullptr);
    gemm_bias_kernel<<<ggrid, 256, gsmem>>>(key,   Wk, bk, Kp, nullptr);
    gemm_bias_kernel<<<ggrid, 256, gsmem>>>(value, Wv, bv, Vp, nullptr);

    const int fsmem = 256 * LDS_ * (int)sizeof(float);   // 69,632 B
    cudaFuncSetAttribute(flash_attn_kernel,
                         cudaFuncAttributeMaxDynamicSharedMemorySize, fsmem);
    flash_attn_kernel<<<dim3(SS / 128, NH, BB), 256, fsmem>>>(mask, causal);

    gemm_bias_kernel<<<ggrid, 256, gsmem>>>(Ap, Wo, bo, out, mask);
}

// round 11
// speedup vs baseline: 1.0845x; 1.0845x over previous
#include <cuda_runtime.h>
#include <cstdint>

// Problem constants
#define BB   2
#define SS   2048
#define TT   2048
#define CHN  1024
#define NH   16
#define HD   64
#define MM   (BB * SS)   // 4096 rows

// Scratch (device globals: allocation-free rule)
__device__ float g_Q[(size_t)MM * CHN];
__device__ float g_K[(size_t)MM * CHN];
__device__ float g_V[(size_t)MM * CHN];
__device__ float g_A[(size_t)MM * CHN];

// ---------------- helpers ----------------
__device__ __forceinline__ uint32_t f2tf(float x) {
    uint32_t u;
    asm("cvt.rna.tf32.f32 %0, %1;\n" : "=r"(u) : "f"(x));
    return u;
}
__device__ __forceinline__ float f2tf_f(float x) {
    return __uint_as_float(f2tf(x));
}
__device__ __forceinline__ uint32_t fu(float x) { return __float_as_uint(x); }

__device__ __forceinline__ float4 tf4(float4 v) {
    return make_float4(f2tf_f(v.x), f2tf_f(v.y), f2tf_f(v.z), f2tf_f(v.w));
}

__device__ __forceinline__ uint32_t smem_u32(const void* p) {
    return (uint32_t)__cvta_generic_to_shared(p);
}

// D(16x8) += A(16x8, tf32, row) * B(8x8, tf32, col)
__device__ __forceinline__ void mma8(float c[4], const uint32_t a[4], const uint32_t b[2]) {
    asm volatile(
        "mma.sync.aligned.m16n8k8.row.col.f32.tf32.tf32.f32 "
        "{%0,%1,%2,%3}, {%4,%5,%6,%7}, {%8,%9}, {%0,%1,%2,%3};\n"
        : "+f"(c[0]), "+f"(c[1]), "+f"(c[2]), "+f"(c[3])
        : "r"(a[0]), "r"(a[1]), "r"(a[2]), "r"(a[3]), "r"(b[0]), "r"(b[1]));
}

// ldmatrix x4: 4 8x8-b16 matrices (= 8x4-tf32 blocks); exact tf32 frag layout.
__device__ __forceinline__ void ldsm_x4(uint32_t r[4], uint32_t saddr) {
    asm volatile("ldmatrix.sync.aligned.m8n8.x4.shared.b16 {%0,%1,%2,%3}, [%4];"
        : "=r"(r[0]), "=r"(r[1]), "=r"(r[2]), "=r"(r[3]) : "r"(saddr));
}

// ---------------- GEMM body (R9-proven): C[4096,1024] = X @ W + bias ----------------
// BM=128, BN=128, BK=32, 256 threads (8 warps = 4m x 2n), LDSM fragments,
// double-buffered smem + register prefetch.
#define GXF   (128 * 36)
#define GWF   (128 * 36)
#define GSTG  (GXF + GWF)
#define GSTGB (GSTG * 4)

__device__ __forceinline__ void gemm_body(
    const float* __restrict__ X, const float* __restrict__ W,
    const float* __restrict__ bias, float* __restrict__ C,
    const float* __restrict__ maskScale, float* gsm)
{
    const uint32_t gsb = smem_u32(gsm);

    const int tid  = threadIdx.x;
    const int lane = tid & 31;
    const int warp = tid >> 5;
    const int g    = lane >> 2;
    const int tg   = lane & 3;
    const int wm   = warp >> 1;   // 0..3
    const int wn   = warp & 1;    // 0..1
    const int m0   = blockIdx.y * 128;
    const int n0   = blockIdx.x * 128;

    const uint32_t a_thr = (uint32_t)(((wm * 32 + (lane & 15)) * 36 + (lane >> 4) * 4) * 4);
    const uint32_t b_thr = (uint32_t)(((wn * 64 + ((lane >> 4) * 8) + (lane & 7)) * 36
                                      + (((lane >> 3) & 1) * 4)) * 4);

    float4 px[4], pw[4];

    auto ldg_tile = [&](int kt) {
#pragma unroll
        for (int i = 0; i < 4; i++) {
            int idx = i * 256 + tid;
            int xr = idx >> 3, xc = (idx & 7) * 4;
            px[i] = *(const float4*)&X[(size_t)(m0 + xr) * 1024 + kt + xc];
        }
        const int bn = tid & 127;
        const int bh = tid >> 7;
#pragma unroll
        for (int j = 0; j < 4; j++) {
            int kq = bh * 4 + j;
            pw[j] = make_float4(
                W[(size_t)(kt + kq * 4 + 0) * 1024 + n0 + bn],
                W[(size_t)(kt + kq * 4 + 1) * 1024 + n0 + bn],
                W[(size_t)(kt + kq * 4 + 2) * 1024 + n0 + bn],
                W[(size_t)(kt + kq * 4 + 3) * 1024 + n0 + bn]);
        }
    };
    auto sts_tile = [&](int st) {
        float* Xs = gsm + st * GSTG;
        float* Ws = Xs + GXF;
#pragma unroll
        for (int i = 0; i < 4; i++) {
            int idx = i * 256 + tid;
            int xr = idx >> 3, xc = (idx & 7) * 4;
            *(float4*)&Xs[xr * 36 + xc] = tf4(px[i]);
        }
        const int bn = tid & 127;
        const int bh = tid >> 7;
#pragma unroll
        for (int j = 0; j < 4; j++) {
            int kq = bh * 4 + j;
            *(float4*)&Ws[bn * 36 + kq * 4] = tf4(pw[j]);
        }
    };

    float c[2][8][4];
#pragma unroll
    for (int mt = 0; mt < 2; mt++)
#pragma unroll
        for (int nt = 0; nt < 8; nt++)
#pragma unroll
            for (int e = 0; e < 4; e++) c[mt][nt][e] = 0.f;

    ldg_tile(0);
    sts_tile(0);
    __syncthreads();

    for (int kt = 0; kt < 32; kt++) {
        if (kt + 1 < 32) ldg_tile((kt + 1) * 32);

        const uint32_t xa = gsb + (kt & 1) * GSTGB + a_thr;
        const uint32_t wa = gsb + (kt & 1) * GSTGB + GXF * 4 + b_thr;

#pragma unroll
        for (int kk = 0; kk < 4; kk++) {
            uint32_t af[2][4], bf[4][4];
            ldsm_x4(af[0], xa + kk * 32);
            ldsm_x4(af[1], xa + 16 * 36 * 4 + kk * 32);
#pragma unroll
            for (int p = 0; p < 4; p++)
                ldsm_x4(bf[p], wa + p * (16 * 36 * 4) + kk * 32);
#pragma unroll
            for (int p = 0; p < 4; p++) {
                mma8(c[0][2 * p],     af[0], &bf[p][0]);
                mma8(c[0][2 * p + 1], af[0], &bf[p][2]);
                mma8(c[1][2 * p],     af[1], &bf[p][0]);
                mma8(c[1][2 * p + 1], af[1], &bf[p][2]);
            }
        }

        if (kt + 1 < 32) sts_tile((kt + 1) & 1);
        __syncthreads();
    }

#pragma unroll
    for (int mt = 0; mt < 2; mt++) {
        int r0 = m0 + wm * 32 + mt * 16 + g;
        int r1 = r0 + 8;
        float sc0 = 1.f, sc1 = 1.f;
        if (maskScale) {
            sc0 = maskScale[(size_t)r0 * TT];
            sc1 = maskScale[(size_t)r1 * TT];
        }
#pragma unroll
        for (int nt = 0; nt < 8; nt++) {
            int col = n0 + wn * 64 + nt * 8 + 2 * tg;
            float b0 = bias[col], b1 = bias[col + 1];
            float2 v0 = make_float2((c[mt][nt][0] + b0) * sc0, (c[mt][nt][1] + b1) * sc0);
            float2 v1 = make_float2((c[mt][nt][2] + b0) * sc1, (c[mt][nt][3] + b1) * sc1);
            *(float2*)&C[(size_t)r0 * 1024 + col] = v0;
            *(float2*)&C[(size_t)r1 * 1024 + col] = v1;
        }
    }
}

// Fused QKV projections: blockIdx.z = 0/1/2 -> (query,Wq,bq,g_Q) / (key,...) / (value,...)
__global__ void __launch_bounds__(256, 2) qkv_gemm_kernel(
    const float* __restrict__ query, const float* __restrict__ key,
    const float* __restrict__ value,
    const float* __restrict__ Wq, const float* __restrict__ Wk,
    const float* __restrict__ Wv,
    const float* __restrict__ bq, const float* __restrict__ bk,
    const float* __restrict__ bv,
    float* __restrict__ Qp, float* __restrict__ Kp, float* __restrict__ Vp)
{
    extern __shared__ float gsm[];
    const int z = blockIdx.z;   // uniform per CTA
    const float* X    = (z == 0) ? query : (z == 1) ? key : value;
    const float* W    = (z == 0) ? Wq    : (z == 1) ? Wk  : Wv;
    const float* bias = (z == 0) ? bq    : (z == 1) ? bk  : bv;
    float*       C    = (z == 0) ? Qp    : (z == 1) ? Kp  : Vp;
    gemm_body(X, W, bias, C, nullptr, gsm);
}

// Output projection (with mask scaling)
__global__ void __launch_bounds__(256, 2) out_gemm_kernel(
    const float* __restrict__ X, const float* __restrict__ W,
    const float* __restrict__ bias, float* __restrict__ C,
    const float* __restrict__ maskScale)
{
    extern __shared__ float gsm[];
    gemm_body(X, W, bias, C, maskScale, gsm);
}

// ---------------- Flash attention (exact R9 restore: proven 307us) ----------------
// Grid: (S/128, H, B). 128 threads = 4 warps; warp w owns q-rows [32w,32w+32)
// as 2 m-tiles. Ks: [t][d] stride 68. Vs: [d][t] stride 68 (transposed fill).
// P round-trips through Qs (own warp rows only). LDSM fragments.
#define LDS_  68
#define FCH   64
#define NCH   (TT / FCH)

__global__ void __launch_bounds__(128) flash_attn_kernel(
    const float* __restrict__ mask, const int* __restrict__ causal_p)
{
    extern __shared__ float sm[];
    float* Qs = sm;                     // 128 x 68
    float* Ks = sm + 128 * LDS_;        // 64 x 68  [t][d]
    float* Vs = sm + 192 * LDS_;        // 64 x 68  [d][t]

    const int tid  = threadIdx.x;
    const int lane = tid & 31;
    const int warp = tid >> 5;
    const int g    = lane >> 2;
    const int tg   = lane & 3;
    const int s0   = blockIdx.x * 128;
    const int h    = blockIdx.y;
    const int b    = blockIdx.z;
    const int causal = causal_p[0];

    const uint32_t Qs_u = smem_u32(Qs);
    const uint32_t Ks_u = smem_u32(Ks);
    const uint32_t Vs_u = smem_u32(Vs);

    const uint32_t bK = Ks_u + (uint32_t)(((((lane >> 4) * 8) + (lane & 7)) * LDS_
                                           + (((lane >> 3) & 1) * 4)) * 4);
    const uint32_t bV = Vs_u + (uint32_t)(((((lane >> 4) * 8) + (lane & 7)) * LDS_
                                           + (((lane >> 3) & 1) * 4)) * 4);
    const uint32_t aP0 = Qs_u + (uint32_t)(((warp * 32 + (lane & 15)) * LDS_
                                            + ((lane >> 4) * 4)) * 4);
    const uint32_t aP1 = aP0 + (uint32_t)(16 * LDS_ * 4);

    const size_t qoff = ((size_t)b * SS + s0) * CHN + h * HD;
#pragma unroll
    for (int i = 0; i < 16; i++) {
        int idx = i * 128 + tid;
        int r = idx >> 4, cc = (idx & 15) * 4;
        float4 v = *(const float4*)&g_Q[qoff + (size_t)r * CHN + cc];
        *(float4*)&Qs[r * LDS_ + cc] = tf4(v);
    }
    __syncthreads();

    uint32_t qa[2][8][4];
#pragma unroll
    for (int mt = 0; mt < 2; mt++) {
        uint32_t base = (mt == 0) ? aP0 : aP1;
#pragma unroll
        for (int j = 0; j < 8; j++) ldsm_x4(qa[mt][j], base + j * 32);
    }

    float o[2][8][4];
#pragma unroll
    for (int mt = 0; mt < 2; mt++)
#pragma unroll
        for (int nt = 0; nt < 8; nt++)
#pragma unroll
            for (int e = 0; e < 4; e++) o[mt][nt][e] = 0.f;
    float mr[2][2] = {{-1e30f, -1e30f}, {-1e30f, -1e30f}};
    float lr[2][2] = {{0.f, 0.f}, {0.f, 0.f}};

    const float* mb = mask + (size_t)b * SS * TT;
    const int vd  = tid & 63;
    const int vth = tid >> 6;

    for (int ic = 0; ic < NCH; ic++) {
        const int t0 = ic * FCH;
        __syncthreads();

        const size_t kvoff = ((size_t)b * TT + t0) * CHN + h * HD;
#pragma unroll
        for (int i = 0; i < 8; i++) {
            int idx = i * 128 + tid;
            int r = idx >> 4, cc = (idx & 15) * 4;
            float4 kv = *(const float4*)&g_K[kvoff + (size_t)r * CHN + cc];
            *(float4*)&Ks[r * LDS_ + cc] = tf4(kv);
        }
#pragma unroll
        for (int q8 = 0; q8 < 8; q8++) {
            int q = vth * 8 + q8;
            float4 vv = make_float4(
                g_V[kvoff + (size_t)(q * 4 + 0) * CHN + vd],
                g_V[kvoff + (size_t)(q * 4 + 1) * CHN + vd],
                g_V[kvoff + (size_t)(q * 4 + 2) * CHN + vd],
                g_V[kvoff + (size_t)(q * 4 + 3) * CHN + vd]);
            *(float4*)&Vs[vd * LDS_ + q * 4] = tf4(vv);
        }
        __syncthreads();

        float s[2][8][4];
#pragma unroll
        for (int mt = 0; mt < 2; mt++)
#pragma unroll
            for (int nt = 0; nt < 8; nt++)
#pragma unroll
                for (int e = 0; e < 4; e++) s[mt][nt][e] = 0.f;
#pragma unroll
        for (int ks = 0; ks < 8; ks++) {
            uint32_t kf[4][4];
#pragma unroll
            for (int p = 0; p < 4; p++)
                ldsm_x4(kf[p], bK + p * (16 * LDS_ * 4) + ks * 32);
#pragma unroll
            for (int p = 0; p < 4; p++) {
                mma8(s[0][2 * p],     qa[0][ks], &kf[p][0]);
                mma8(s[0][2 * p + 1], qa[0][ks], &kf[p][2]);
                mma8(s[1][2 * p],     qa[1][ks], &kf[p][0]);
                mma8(s[1][2 * p + 1], qa[1][ks], &kf[p][2]);
            }
        }

        if (!causal) {
            bool mz[8][2];
#pragma unroll
            for (int nt = 0; nt < 8; nt++)
#pragma unroll
                for (int e = 0; e < 2; e++)
                    mz[nt][e] = (mb[t0 + nt * 8 + 2 * tg + e] == 0.f);
#pragma unroll
            for (int mt = 0; mt < 2; mt++)
#pragma unroll
                for (int nt = 0; nt < 8; nt++)
#pragma unroll
                    for (int e = 0; e < 2; e++) {
                        s[mt][nt][e]     = mz[nt][e] ? -1e30f : s[mt][nt][e] * 0.125f;
                        s[mt][nt][2 + e] = mz[nt][e] ? -1e30f : s[mt][nt][2 + e] * 0.125f;
                    }
        } else {
#pragma unroll
            for (int mt = 0; mt < 2; mt++) {
                int rg0 = s0 + warp * 32 + mt * 16 + g;
                int rg1 = rg0 + 8;
#pragma unroll
                for (int nt = 0; nt < 8; nt++) {
#pragma unroll
                    for (int e = 0; e < 2; e++) {
                        int t = t0 + nt * 8 + 2 * tg + e;
                        float v0 = s[mt][nt][e] * 0.125f;
                        float v1 = s[mt][nt][2 + e] * 0.125f;
                        if (mb[(size_t)rg0 * TT + t] == 0.f && t <= rg0) v0 = -1e30f;
                        if (mb[(size_t)rg1 * TT + t] == 0.f && t <= rg1) v1 = -1e30f;
                        s[mt][nt][e] = v0;
                        s[mt][nt][2 + e] = v1;
                    }
                }
            }
        }

#pragma unroll
        for (int mt = 0; mt < 2; mt++) {
            float rm0 = -1e30f, rm1 = -1e30f;
#pragma unroll
            for (int nt = 0; nt < 8; nt++) {
                rm0 = fmaxf(rm0, fmaxf(s[mt][nt][0], s[mt][nt][1]));
                rm1 = fmaxf(rm1, fmaxf(s[mt][nt][2], s[mt][nt][3]));
            }
            rm0 = fmaxf(rm0, __shfl_xor_sync(0xffffffffu, rm0, 1));
            rm0 = fmaxf(rm0, __shfl_xor_sync(0xffffffffu, rm0, 2));
            rm1 = fmaxf(rm1, __shfl_xor_sync(0xffffffffu, rm1, 1));
            rm1 = fmaxf(rm1, __shfl_xor_sync(0xffffffffu, rm1, 2));

            float mn0 = fmaxf(mr[mt][0], rm0);
            float mn1 = fmaxf(mr[mt][1], rm1);
            float a0 = __expf(mr[mt][0] - mn0);
            float a1 = __expf(mr[mt][1] - mn1);
            mr[mt][0] = mn0; mr[mt][1] = mn1;

            int rb = warp * 32 + mt * 16;
            float ls0 = 0.f, ls1 = 0.f;
#pragma unroll
            for (int nt = 0; nt < 8; nt++) {
                float p00 = __expf(s[mt][nt][0] - mn0);
                float p01 = __expf(s[mt][nt][1] - mn0);
                float p10 = __expf(s[mt][nt][2] - mn1);
                float p11 = __expf(s[mt][nt][3] - mn1);
                ls0 += p00 + p01;
                ls1 += p10 + p11;
                int cb = nt * 8 + 2 * tg;
                *(float2*)&Qs[(rb + g) * LDS_ + cb] =
                    make_float2(f2tf_f(p00), f2tf_f(p01));
                *(float2*)&Qs[(rb + g + 8) * LDS_ + cb] =
                    make_float2(f2tf_f(p10), f2tf_f(p11));
                o[mt][nt][0] *= a0; o[mt][nt][1] *= a0;
                o[mt][nt][2] *= a1; o[mt][nt][3] *= a1;
            }
            ls0 += __shfl_xor_sync(0xffffffffu, ls0, 1);
            ls0 += __shfl_xor_sync(0xffffffffu, ls0, 2);
            ls1 += __shfl_xor_sync(0xffffffffu, ls1, 1);
            ls1 += __shfl_xor_sync(0xffffffffu, ls1, 2);
            lr[mt][0] = lr[mt][0] * a0 + ls0;
            lr[mt][1] = lr[mt][1] * a1 + ls1;
        }
        __syncwarp();

#pragma unroll
        for (int ks = 0; ks < 8; ks++) {
            uint32_t pf[2][4], vf[4][4];
            ldsm_x4(pf[0], aP0 + ks * 32);
            ldsm_x4(pf[1], aP1 + ks * 32);
#pragma unroll
            for (int p = 0; p < 4; p++)
                ldsm_x4(vf[p], bV + p * (16 * LDS_ * 4) + ks * 32);
#pragma unroll
            for (int p = 0; p < 4; p++) {
                mma8(o[0][2 * p],     pf[0], &vf[p][0]);
                mma8(o[0][2 * p + 1], pf[0], &vf[p][2]);
                mma8(o[1][2 * p],     pf[1], &vf[p][0]);
                mma8(o[1][2 * p + 1], pf[1], &vf[p][2]);
            }
        }
    }

#pragma unroll
    for (int mt = 0; mt < 2; mt++) {
        float i0 = 1.f / lr[mt][0];
        float i1 = 1.f / lr[mt][1];
        const size_t ob = ((size_t)b * SS + s0 + warp * 32 + mt * 16) * CHN + h * HD;
#pragma unroll
        for (int nt = 0; nt < 8; nt++) {
            int col = nt * 8 + 2 * tg;
            float2 v0 = make_float2(o[mt][nt][0] * i0, o[mt][nt][1] * i0);
            float2 v1 = make_float2(o[mt][nt][2] * i1, o[mt][nt][3] * i1);
            *(float2*)&g_A[ob + (size_t)g * CHN + col] = v0;
            *(float2*)&g_A[ob + (size_t)(g + 8) * CHN + col] = v1;
        }
    }
}

// ---------------- launch ----------------
extern "C" void kernel_launch(void* const* d_in, const int* in_sizes, int n_in,
                              void* d_out, int out_size)
{
    const float* query = (const float*)d_in[0];
    const float* key   = (const float*)d_in[1];
    const float* value = (const float*)d_in[2];
    const float* mask  = (const float*)d_in[3];
    const float* Wq    = (const float*)d_in[4];
    const float* bq    = (const float*)d_in[5];
    const float* Wk    = (const float*)d_in[6];
    const float* bk    = (const float*)d_in[7];
    const float* Wv    = (const float*)d_in[8];
    const float* bv    = (const float*)d_in[9];
    const float* Wo    = (const float*)d_in[10];
    const float* bo    = (const float*)d_in[11];
    const int*   causal = (const int*)d_in[12];
    float* out = (float*)d_out;

    float *Qp, *Kp, *Vp, *Ap;
    cudaGetSymbolAddress((void**)&Qp, g_Q);
    cudaGetSymbolAddress((void**)&Kp, g_K);
    cudaGetSymbolAddress((void**)&Vp, g_V);
    cudaGetSymbolAddress((void**)&Ap, g_A);

    const int gsmem = 2 * GSTGB;   // 73,728 B
    cudaFuncSetAttribute(qkv_gemm_kernel,
                         cudaFuncAttributeMaxDynamicSharedMemorySize, gsmem);
    cudaFuncSetAttribute(out_gemm_kernel,
                         cudaFuncAttributeMaxDynamicSharedMemorySize, gsmem);

    // Fused Q/K/V projections: one launch, 768 CTAs (2.6 full waves vs 3 underfilled)
    qkv_gemm_kernel<<<dim3(8, 32, 3), 256, gsmem>>>(
        query, key, value, Wq, Wk, Wv, bq, bk, bv, Qp, Kp, Vp);

    const int fsmem = 256 * LDS_ * (int)sizeof(float);   // 69,632 B
    cudaFuncSetAttribute(flash_attn_kernel,
                         cudaFuncAttributeMaxDynamicSharedMemorySize, fsmem);
    flash_attn_kernel<<<dim3(SS / 128, NH, BB), 128, fsmem>>>(mask, causal);

    out_gemm_kernel<<<dim3(8, 32), 256, gsmem>>>(Ap, Wo, bo, out, mask);
}